// round 16
// baseline (speedup 1.0000x reference)
#include <cuda_runtime.h>
#include <cuda_fp16.h>
#include <cstdint>

#define BATCH   128
#define IN_DIM  1024
#define OUT_DIM 1024
#define ZD      128

#define ISPLIT  8                    // i-range splits
#define I_PER   (IN_DIM / ISPLIT)    // 128
#define ITERS   I_PER                // 1 i-col per iter
#define RS      80                   // tile row stride (words): 16 mod 32
#define TILEW   (32 * RS)            // words per buffer (32 o-rows)

__device__ float g_xT[IN_DIM * BATCH];   // xT[i*128 + b]

// ---------------- helpers ----------------
__device__ __forceinline__ void mma_fp16(float* c, const uint32_t* a,
                                         uint32_t b0, uint32_t b1) {
    asm volatile(
        "mma.sync.aligned.m16n8k16.row.col.f32.f16.f16.f32 "
        "{%0,%1,%2,%3},{%4,%5,%6,%7},{%8,%9},{%0,%1,%2,%3};"
        : "+f"(c[0]), "+f"(c[1]), "+f"(c[2]), "+f"(c[3])
        : "r"(a[0]), "r"(a[1]), "r"(a[2]), "r"(a[3]), "r"(b0), "r"(b1));
}
__device__ __forceinline__ uint32_t f2h2(float lo, float hi) {
    __half2 h = __float22half2_rn(make_float2(lo, hi));
    return *(uint32_t*)&h;
}
__device__ __forceinline__ uint32_t hmul2u(uint32_t a, uint32_t b) {
    __half2 r = __hmul2(*(__half2*)&a, *(__half2*)&b);
    return *(uint32_t*)&r;
}

// ---------------- k_pre: out = bb + dbb + z@dbW^T + x@(bw+dwb)^T; also x -> g_xT ----------------
__global__ void __launch_bounds__(256)
k_pre(const float* __restrict__ x, const float* __restrict__ z,
      const float* __restrict__ bw, const float* __restrict__ dwb,
      const float* __restrict__ bb, const float* __restrict__ dbW,
      const float* __restrict__ dbb, float* __restrict__ out) {
    __shared__ float as_[16][36];
    __shared__ float wsm[32][36];
    const int t  = threadIdx.x;
    const int o0 = blockIdx.x * 32;
    const int b0 = blockIdx.y * 16;
    const int ty = t >> 4;   // 0..15 batch row
    const int tx = t & 15;   // o cols tx, tx+16
    const int lr = t >> 3;   // 0..31
    const int lc = (t & 7) * 4;
    float acc0 = 0.f, acc1 = 0.f;
    for (int kt = 0; kt < 36; kt++) {
        float4 av, wv;
        if (t < 128) {
            if (kt < 4) av = *(const float4*)(z + (size_t)(b0 + lr) * ZD + kt * 32 + lc);
            else        av = *(const float4*)(x + (size_t)(b0 + lr) * IN_DIM + (kt - 4) * 32 + lc);
        }
        if (kt < 4) {
            wv = *(const float4*)(dbW + (size_t)(o0 + lr) * ZD + kt * 32 + lc);
        } else {
            size_t off = (size_t)(o0 + lr) * IN_DIM + (kt - 4) * 32 + lc;
            float4 a = *(const float4*)(bw + off);
            float4 d = *(const float4*)(dwb + off);
            wv = make_float4(a.x + d.x, a.y + d.y, a.z + d.z, a.w + d.w);
        }
        __syncthreads();
        if (t < 128) *(float4*)&as_[lr & 15][lc] = av;
        *(float4*)&wsm[lr][lc] = wv;
        __syncthreads();
        // transpose side-channel: only o-block 0 writes g_xT for this (b-tile, i-range)
        if (blockIdx.x == 0 && kt >= 4 && t < 128) {
            int il = t >> 2;            // 0..31  local i
            int bl = (t & 3) * 4;       // 0..12  local b (float4)
            float4 v = make_float4(as_[bl][il], as_[bl + 1][il],
                                   as_[bl + 2][il], as_[bl + 3][il]);
            *(float4*)&g_xT[(size_t)((kt - 4) * 32 + il) * BATCH + b0 + bl] = v;
        }
#pragma unroll 8
        for (int j = 0; j < 32; j++) {
            float a = as_[ty][j];
            acc0 += a * wsm[tx][j];
            acc1 += a * wsm[tx + 16][j];
        }
    }
    {
        int o = o0 + tx;
        out[(size_t)(b0 + ty) * OUT_DIM + o]      = acc0 + bb[o] + dbb[o];
        out[(size_t)(b0 + ty) * OUT_DIM + o + 16] = acc1 + bb[o + 16] + dbb[o + 16];
    }
}

// ---------------- k_main: M-operand fp16 MMA, o-tile 32, 1 i-col/iter ----------------
// Tile row r (= o', 0..31), words: base(r) = r*RS + ((r>>1)&1)*4 (parity swizzle)
//   word[base(r) + j*16 + tig*4 + {0,1,2,3}] = {b0(2j), b1(2j), b0(2j+1), b1(2j+1)} for tig.
__global__ void __launch_bounds__(256, 2)
k_main(const float* __restrict__ z, const float* __restrict__ dwW,
       float* __restrict__ out) {
    __shared__ __align__(16) uint32_t ws[2][TILEW];

    const int tid  = threadIdx.x;
    const int w    = tid >> 5;
    const int lane = tid & 31;
    const int g    = lane >> 2;
    const int tig  = lane & 3;
    const int o0   = blockIdx.x * 32;
    const int ibase = blockIdx.y * I_PER;

    // --- z A-fragments for 16 batch rows (w*16+g, +8), register-resident ---
    uint32_t zA[8][4];
    {
        const float* z0 = z + (size_t)(w * 16 + g) * ZD;
        const float* z1 = z0 + 8 * ZD;
#pragma unroll
        for (int kb = 0; kb < 8; kb++) {
            int c = kb * 16 + 2 * tig;
            zA[kb][0] = f2h2(z0[c],     z0[c + 1]);
            zA[kb][1] = f2h2(z1[c],     z1[c + 1]);
            zA[kb][2] = f2h2(z0[c + 8], z0[c + 9]);
            zA[kb][3] = f2h2(z1[c + 8], z1[c + 9]);
        }
    }

    // --- staging: warp w covers o-rows 4w..4w+3; lane: row 4w+(l>>3), qsel = l&7 ---
    const int sr   = w * 4 + (lane >> 3);
    const int qsel = lane & 7;
    const float4* tsrc = (const float4*)(dwW
        + ((size_t)(o0 + sr) * IN_DIM + ibase) * ZD) + qsel;
    // float4 q covers k0 = 4*qsel + 32*q  ->  kb = 2q + (qsel>>2), p = 4*(qsel&3)
    const int e_       = qsel >> 2;
    const int tigbase  = ((qsel & 3) & 1) * 2;
    const int halfsel  = (qsel & 3) >> 1;
    const int sb0 = sr * RS + ((sr >> 1) & 1) * 4 + tigbase * 4 + e_ * 2 + halfsel;

    float4 pre[4];
#define LDG_TILE(itv)                                                          \
    do {                                                                       \
        const float4* p = tsrc + (size_t)(itv) * 32;                           \
        pre[0] = __ldg(p);                                                     \
        pre[1] = __ldg(p + 8);                                                 \
        pre[2] = __ldg(p + 16);                                                \
        pre[3] = __ldg(p + 24);                                                \
    } while (0)
#define STS_TILE(bsel)                                                         \
    do {                                                                       \
        uint32_t* d = &ws[bsel][sb0];                                          \
        d[0]      = f2h2(pre[0].x, pre[0].y);  d[4]      = f2h2(pre[0].z, pre[0].w); \
        d[16]     = f2h2(pre[1].x, pre[1].y);  d[20]     = f2h2(pre[1].z, pre[1].w); \
        d[32]     = f2h2(pre[2].x, pre[2].y);  d[36]     = f2h2(pre[2].z, pre[2].w); \
        d[48]     = f2h2(pre[3].x, pre[3].y);  d[52]     = f2h2(pre[3].z, pre[3].w); \
    } while (0)

    LDG_TILE(0);
    STS_TILE(0);
    LDG_TILE(1);
    __syncthreads();

    float c[4][4] = {};   // [nb][frag]

#pragma unroll 1
    for (int it = 0; it < ITERS; ++it) {
        // x for this i-col (broadcast loads)
        const float* xcol = g_xT + (size_t)(ibase + it) * BATCH + w * 16 + g;
        float x0 = __ldg(xcol);
        float x1 = __ldg(xcol + 8);
        const uint32_t xh0 = f2h2(x0, x0);
        const uint32_t xh1 = f2h2(x1, x1);

        if (it + 1 < ITERS) STS_TILE((it + 1) & 1);
        if (it + 2 < ITERS) LDG_TILE(it + 2);

        const uint32_t* rb_ = &ws[it & 1][0];
#pragma unroll
        for (int j = 0; j < 4; j++) {
            uint32_t saE[4], saO[4];
            saE[0] = hmul2u(zA[2 * j][0], xh0);
            saE[1] = hmul2u(zA[2 * j][1], xh1);
            saE[2] = hmul2u(zA[2 * j][2], xh0);
            saE[3] = hmul2u(zA[2 * j][3], xh1);
            saO[0] = hmul2u(zA[2 * j + 1][0], xh0);
            saO[1] = hmul2u(zA[2 * j + 1][1], xh1);
            saO[2] = hmul2u(zA[2 * j + 1][2], xh0);
            saO[3] = hmul2u(zA[2 * j + 1][3], xh1);
#pragma unroll
            for (int nb = 0; nb < 4; nb++) {
                const int row = nb * 8 + g;
                uint4 v = *(const uint4*)(rb_ + row * RS + ((row >> 1) & 1) * 4
                                              + j * 16 + tig * 4);
                mma_fp16(c[nb], saE, v.x, v.y);
                mma_fp16(c[nb], saO, v.z, v.w);
            }
        }
        __syncthreads();
    }
#undef STS_TILE
#undef LDG_TILE

    // --- final: direct accumulate (ISPLIT contenders per cell) ---
    const int br = w * 16 + g;
#pragma unroll
    for (int nb = 0; nb < 4; nb++) {
        int ob = o0 + nb * 8 + 2 * tig;
        atomicAdd(&out[(size_t)br * OUT_DIM + ob],           c[nb][0]);
        atomicAdd(&out[(size_t)br * OUT_DIM + ob + 1],       c[nb][1]);
        atomicAdd(&out[(size_t)(br + 8) * OUT_DIM + ob],     c[nb][2]);
        atomicAdd(&out[(size_t)(br + 8) * OUT_DIM + ob + 1], c[nb][3]);
    }
}

// ---------------- launch ----------------
extern "C" void kernel_launch(void* const* d_in, const int* in_sizes, int n_in,
                              void* d_out, int out_size) {
    const float* x   = (const float*)d_in[0];
    const float* z   = (const float*)d_in[1];
    const float* bw  = (const float*)d_in[2];
    const float* dwW = (const float*)d_in[3];
    const float* dwb = (const float*)d_in[4];
    const float* bb  = (const float*)d_in[5];
    const float* dbW = (const float*)d_in[6];
    const float* dbb = (const float*)d_in[7];
    float* out = (float*)d_out;

    k_pre<<<dim3(OUT_DIM / 32, BATCH / 16), 256>>>(x, z, bw, dwb, bb, dbW, dbb, out);
    k_main<<<dim3(OUT_DIM / 32, ISPLIT), 256>>>(z, dwW, out);
}

// round 17
// speedup vs baseline: 1.0756x; 1.0756x over previous
#include <cuda_runtime.h>
#include <cuda_fp16.h>
#include <cstdint>

#define BATCH   128
#define IN_DIM  1024
#define OUT_DIM 1024
#define ZD      128

#define ISPLIT  8                    // i-range splits
#define I_PER   (IN_DIM / ISPLIT)    // 128
#define NIT     2                    // i-cols per barrier period
#define PERIODS (I_PER / NIT)        // 64
#define RS      80                   // tile row stride (words): 16 mod 32
#define TILEW   (32 * RS)            // words per (buffer, col)

__device__ float g_xT[IN_DIM * BATCH];   // xT[i*128 + b]

// ---------------- helpers ----------------
__device__ __forceinline__ void mma_fp16(float* c, const uint32_t* a,
                                         uint32_t b0, uint32_t b1) {
    asm volatile(
        "mma.sync.aligned.m16n8k16.row.col.f32.f16.f16.f32 "
        "{%0,%1,%2,%3},{%4,%5,%6,%7},{%8,%9},{%0,%1,%2,%3};"
        : "+f"(c[0]), "+f"(c[1]), "+f"(c[2]), "+f"(c[3])
        : "r"(a[0]), "r"(a[1]), "r"(a[2]), "r"(a[3]), "r"(b0), "r"(b1));
}
__device__ __forceinline__ uint32_t f2h2(float lo, float hi) {
    __half2 h = __float22half2_rn(make_float2(lo, hi));
    return *(uint32_t*)&h;
}
__device__ __forceinline__ uint32_t hmul2u(uint32_t a, uint32_t b) {
    __half2 r = __hmul2(*(__half2*)&a, *(__half2*)&b);
    return *(uint32_t*)&r;
}

// ---------------- k_pre: out = bb + dbb + z@dbW^T + x@(bw+dwb)^T; also x -> g_xT ----------------
// grid (32 o-tiles, 2 b-halves of 64): bw+dwb read only 2x.
__global__ void __launch_bounds__(256)
k_pre(const float* __restrict__ x, const float* __restrict__ z,
      const float* __restrict__ bw, const float* __restrict__ dwb,
      const float* __restrict__ bb, const float* __restrict__ dbW,
      const float* __restrict__ dbb, float* __restrict__ out) {
    __shared__ float as_[64][36];
    __shared__ float wsm[32][36];
    const int t  = threadIdx.x;
    const int o0 = blockIdx.x * 32;
    const int b0 = blockIdx.y * 64;
    const int ty = t >> 4;   // 0..15 -> 4 batch rows each
    const int tx = t & 15;   // o cols tx, tx+16
    float acc[4][2] = {};
    for (int kt = 0; kt < 36; kt++) {
        // prefetch stage data: a-tile 64x32 (2 tasks/thread), w-tile 32x32 (1 task)
        float4 av0, av1, wv;
        {
            int task0 = t, task1 = t + 256;
            int r0 = task0 >> 3, c0 = (task0 & 7) * 4;
            int r1 = task1 >> 3, c1 = (task1 & 7) * 4;
            if (kt < 4) {
                av0 = *(const float4*)(z + (size_t)(b0 + r0) * ZD + kt * 32 + c0);
                av1 = *(const float4*)(z + (size_t)(b0 + r1) * ZD + kt * 32 + c1);
            } else {
                av0 = *(const float4*)(x + (size_t)(b0 + r0) * IN_DIM + (kt - 4) * 32 + c0);
                av1 = *(const float4*)(x + (size_t)(b0 + r1) * IN_DIM + (kt - 4) * 32 + c1);
            }
            int wr = t >> 3, wc = (t & 7) * 4;
            if (kt < 4) {
                wv = *(const float4*)(dbW + (size_t)(o0 + wr) * ZD + kt * 32 + wc);
            } else {
                size_t off = (size_t)(o0 + wr) * IN_DIM + (kt - 4) * 32 + wc;
                float4 a = *(const float4*)(bw + off);
                float4 d = *(const float4*)(dwb + off);
                wv = make_float4(a.x + d.x, a.y + d.y, a.z + d.z, a.w + d.w);
            }
        }
        __syncthreads();
        {
            int task0 = t, task1 = t + 256;
            *(float4*)&as_[task0 >> 3][(task0 & 7) * 4] = av0;
            *(float4*)&as_[task1 >> 3][(task1 & 7) * 4] = av1;
            *(float4*)&wsm[t >> 3][(t & 7) * 4] = wv;
        }
        __syncthreads();
        // transpose side-channel: o-block 0 writes g_xT for this (b-half, i-range)
        if (blockIdx.x == 0 && kt >= 4) {
            int il = t >> 3;            // 0..31 local i
            int bl = (t & 7) * 8;       // 0..56 local b
            float4 v0 = make_float4(as_[bl][il], as_[bl + 1][il],
                                    as_[bl + 2][il], as_[bl + 3][il]);
            float4 v1 = make_float4(as_[bl + 4][il], as_[bl + 5][il],
                                    as_[bl + 6][il], as_[bl + 7][il]);
            float* dst = &g_xT[(size_t)((kt - 4) * 32 + il) * BATCH + b0 + bl];
            *(float4*)dst = v0;
            *(float4*)(dst + 4) = v1;
        }
#pragma unroll 8
        for (int j = 0; j < 32; j++) {
            float w0 = wsm[tx][j], w1 = wsm[tx + 16][j];
#pragma unroll
            for (int p = 0; p < 4; p++) {
                float a = as_[ty * 4 + p][j];
                acc[p][0] += a * w0;
                acc[p][1] += a * w1;
            }
        }
    }
#pragma unroll
    for (int p = 0; p < 4; p++) {
        int o = o0 + tx;
        int br = b0 + ty * 4 + p;
        out[(size_t)br * OUT_DIM + o]      = acc[p][0] + bb[o] + dbb[o];
        out[(size_t)br * OUT_DIM + o + 16] = acc[p][1] + bb[o + 16] + dbb[o + 16];
    }
}

// ---------------- k_main: M-operand fp16 MMA, o-tile 32, 2 i-cols per barrier ----------------
__global__ void __launch_bounds__(256, 2)
k_main(const float* __restrict__ z, const float* __restrict__ dwW,
       float* __restrict__ out) {
    __shared__ __align__(16) uint32_t ws[2][NIT][TILEW];

    const int tid  = threadIdx.x;
    const int w    = tid >> 5;
    const int lane = tid & 31;
    const int g    = lane >> 2;
    const int tig  = lane & 3;
    const int o0   = blockIdx.x * 32;
    const int ibase = blockIdx.y * I_PER;

    // --- z A-fragments for 16 batch rows (w*16+g, +8), register-resident ---
    uint32_t zA[8][4];
    {
        const float* z0 = z + (size_t)(w * 16 + g) * ZD;
        const float* z1 = z0 + 8 * ZD;
#pragma unroll
        for (int kb = 0; kb < 8; kb++) {
            int c = kb * 16 + 2 * tig;
            zA[kb][0] = f2h2(z0[c],     z0[c + 1]);
            zA[kb][1] = f2h2(z1[c],     z1[c + 1]);
            zA[kb][2] = f2h2(z0[c + 8], z0[c + 9]);
            zA[kb][3] = f2h2(z1[c + 8], z1[c + 9]);
        }
    }

    // --- staging geometry (as R16): warp w -> o-rows 4w..4w+3 ---
    const int sr   = w * 4 + (lane >> 3);
    const int qsel = lane & 7;
    const float4* tsrc = (const float4*)(dwW
        + ((size_t)(o0 + sr) * IN_DIM + ibase) * ZD) + qsel;
    const int e_      = qsel >> 2;
    const int tigbase = ((qsel & 3) & 1) * 2;
    const int halfsel = (qsel & 3) >> 1;
    const int sb0 = sr * RS + ((sr >> 1) & 1) * 4 + tigbase * 4 + e_ * 2 + halfsel;

    uint32_t pre_h[NIT][8];   // converted fp16 staging data, one period

#define LDGCVT(perv, cc)                                                       \
    do {                                                                       \
        const float4* p = tsrc + (size_t)((perv) * NIT + (cc)) * 32;           \
        float4 q0 = __ldg(p);                                                  \
        float4 q1 = __ldg(p + 8);                                              \
        float4 q2 = __ldg(p + 16);                                             \
        float4 q3 = __ldg(p + 24);                                             \
        pre_h[cc][0] = f2h2(q0.x, q0.y);  pre_h[cc][1] = f2h2(q0.z, q0.w);     \
        pre_h[cc][2] = f2h2(q1.x, q1.y);  pre_h[cc][3] = f2h2(q1.z, q1.w);     \
        pre_h[cc][4] = f2h2(q2.x, q2.y);  pre_h[cc][5] = f2h2(q2.z, q2.w);     \
        pre_h[cc][6] = f2h2(q3.x, q3.y);  pre_h[cc][7] = f2h2(q3.z, q3.w);     \
    } while (0)
#define STS_COL(bsel, cc)                                                      \
    do {                                                                       \
        uint32_t* d = &ws[bsel][cc][sb0];                                      \
        d[0]  = pre_h[cc][0];  d[4]  = pre_h[cc][1];                           \
        d[16] = pre_h[cc][2];  d[20] = pre_h[cc][3];                           \
        d[32] = pre_h[cc][4];  d[36] = pre_h[cc][5];                           \
        d[48] = pre_h[cc][6];  d[52] = pre_h[cc][7];                           \
    } while (0)

    // prologue: period 0 -> buf0 ; period 1 -> pre_h ; x for period 0
    LDGCVT(0, 0);  LDGCVT(0, 1);
    STS_COL(0, 0); STS_COL(0, 1);
    LDGCVT(1, 0);  LDGCVT(1, 1);

    float xcur[NIT][2], xnxt[NIT][2];
#pragma unroll
    for (int cc = 0; cc < NIT; cc++) {
        const float* xc = g_xT + (size_t)(ibase + cc) * BATCH + w * 16 + g;
        xcur[cc][0] = __ldg(xc);
        xcur[cc][1] = __ldg(xc + 8);
    }
    __syncthreads();

    float c[4][4] = {};   // [nb][frag]

#pragma unroll 1
    for (int pit = 0; pit < PERIODS; ++pit) {
        // stage period pit+1; prefetch period pit+2; prefetch x for pit+1
        if (pit + 1 < PERIODS) {
            STS_COL((pit + 1) & 1, 0);
            STS_COL((pit + 1) & 1, 1);
        }
        if (pit + 2 < PERIODS) {
            LDGCVT(pit + 2, 0);
            LDGCVT(pit + 2, 1);
        }
        if (pit + 1 < PERIODS) {
#pragma unroll
            for (int cc = 0; cc < NIT; cc++) {
                const float* xc = g_xT
                    + (size_t)(ibase + (pit + 1) * NIT + cc) * BATCH + w * 16 + g;
                xnxt[cc][0] = __ldg(xc);
                xnxt[cc][1] = __ldg(xc + 8);
            }
        }

        // compute both i-cols of period pit
#pragma unroll
        for (int cc = 0; cc < NIT; cc++) {
            const uint32_t* rb_ = &ws[pit & 1][cc][0];
            const uint32_t xh0 = f2h2(xcur[cc][0], xcur[cc][0]);
            const uint32_t xh1 = f2h2(xcur[cc][1], xcur[cc][1]);
#pragma unroll
            for (int j = 0; j < 4; j++) {
                uint32_t saE[4], saO[4];
                saE[0] = hmul2u(zA[2 * j][0], xh0);
                saE[1] = hmul2u(zA[2 * j][1], xh1);
                saE[2] = hmul2u(zA[2 * j][2], xh0);
                saE[3] = hmul2u(zA[2 * j][3], xh1);
                saO[0] = hmul2u(zA[2 * j + 1][0], xh0);
                saO[1] = hmul2u(zA[2 * j + 1][1], xh1);
                saO[2] = hmul2u(zA[2 * j + 1][2], xh0);
                saO[3] = hmul2u(zA[2 * j + 1][3], xh1);
#pragma unroll
                for (int nb = 0; nb < 4; nb++) {
                    const int row = nb * 8 + g;
                    uint4 v = *(const uint4*)(rb_ + row * RS + ((row >> 1) & 1) * 4
                                                  + j * 16 + tig * 4);
                    mma_fp16(c[nb], saE, v.x, v.y);
                    mma_fp16(c[nb], saO, v.z, v.w);
                }
            }
        }
        __syncthreads();
#pragma unroll
        for (int cc = 0; cc < NIT; cc++) {
            xcur[cc][0] = xnxt[cc][0];
            xcur[cc][1] = xnxt[cc][1];
        }
    }
#undef STS_COL
#undef LDGCVT

    // --- final: direct accumulate (ISPLIT contenders per cell) ---
    const int br = w * 16 + g;
#pragma unroll
    for (int nb = 0; nb < 4; nb++) {
        int ob = o0 + nb * 8 + 2 * tig;
        atomicAdd(&out[(size_t)br * OUT_DIM + ob],           c[nb][0]);
        atomicAdd(&out[(size_t)br * OUT_DIM + ob + 1],       c[nb][1]);
        atomicAdd(&out[(size_t)(br + 8) * OUT_DIM + ob],     c[nb][2]);
        atomicAdd(&out[(size_t)(br + 8) * OUT_DIM + ob + 1], c[nb][3]);
    }
}

// ---------------- launch ----------------
extern "C" void kernel_launch(void* const* d_in, const int* in_sizes, int n_in,
                              void* d_out, int out_size) {
    const float* x   = (const float*)d_in[0];
    const float* z   = (const float*)d_in[1];
    const float* bw  = (const float*)d_in[2];
    const float* dwW = (const float*)d_in[3];
    const float* dwb = (const float*)d_in[4];
    const float* bb  = (const float*)d_in[5];
    const float* dbW = (const float*)d_in[6];
    const float* dbb = (const float*)d_in[7];
    float* out = (float*)d_out;

    k_pre<<<dim3(OUT_DIM / 32, BATCH / 64), 256>>>(x, z, bw, dwb, bb, dbW, dbb, out);
    k_main<<<dim3(OUT_DIM / 32, ISPLIT), 256>>>(z, dwW, out);
}